// round 9
// baseline (speedup 1.0000x reference)
#include <cuda_runtime.h>
#include <cuda_fp16.h>
#include <math.h>

#define D 64
#define NMAX 100000
#define EMAX 1600000

// Scratch (__device__ globals, allocation-free rule)
__device__ __half2 g_xwp[(size_t)NMAX * 64];   // (xw_low[c], xw_high[c]) per col
__device__ float   g_mlp[(size_t)NMAX * 64];   // relu(x@W_mlp)
__device__ __half2 g_rel[(size_t)NMAX * 64];   // relu'd spmm result, packed (low, high)
__device__ int     g_deg[NMAX];
__device__ int     g_rowstart[NMAX];
__device__ int     g_cursor[NMAX];
__device__ int2    g_cedge[EMAX];              // .x = src|(k<<20), .y = half2(vl,vh) bits

// ---------------- CSR build ----------------

__global__ void zero_deg_kernel(int n) {
    int i = blockIdx.x * blockDim.x + threadIdx.x;
    if (i < n) g_deg[i] = 0;
}

__global__ void hist_kernel(const int* __restrict__ dst, int e) {
    int i = blockIdx.x * blockDim.x + threadIdx.x;
    if (i < e) atomicAdd(&g_deg[dst[i]], 1);
}

// One-block exclusive scan over g_deg -> g_rowstart, g_cursor.
__global__ void scan_kernel(int n) {
    __shared__ int ssum[1024];
    int t = threadIdx.x;
    int chunk = (n + 1023) >> 10;
    int lo = t * chunk;
    int hi = min(lo + chunk, n);
    int s = 0;
    for (int i = lo; i < hi; i++) s += g_deg[i];
    ssum[t] = s;
    __syncthreads();
    for (int d = 1; d < 1024; d <<= 1) {
        int v = (t >= d) ? ssum[t - d] : 0;
        __syncthreads();
        ssum[t] += v;
        __syncthreads();
    }
    int off = ssum[t] - s;
    for (int i = lo; i < hi; i++) {
        g_rowstart[i] = off;
        g_cursor[i] = off;
        off += g_deg[i];
    }
}

__global__ void scatter_kernel(const int* __restrict__ src,
                               const int* __restrict__ dst,
                               const int* __restrict__ lab,
                               const float* __restrict__ vl,
                               const float* __restrict__ vh,
                               int e) {
    int i = blockIdx.x * blockDim.x + threadIdx.x;
    if (i >= e) return;
    int s = src[i], d = dst[i];
    int sl = lab[s], dl = lab[d];
    int k = ((sl | dl) < 0) ? 2 : ((sl != dl) ? 1 : 0);
    int pos = atomicAdd(&g_cursor[d], 1);
    __half2 cv = __floats2half2_rn(vl[i], vh[i]);
    g_cedge[pos] = make_int2(s | (k << 20), *(int*)&cv);
}

// ---------------- dense 3-way GEMM ----------------

__global__ void gemm3_kernel(const float* __restrict__ x,
                             const float* __restrict__ wl,
                             const float* __restrict__ wh,
                             const float* __restrict__ wm,
                             int n) {
    __shared__ float sW[3][D][D];
    for (int i = threadIdx.x; i < D * D; i += blockDim.x) {
        sW[0][i >> 6][i & 63] = wl[i];
        sW[1][i >> 6][i & 63] = wh[i];
        sW[2][i >> 6][i & 63] = wm[i];
    }
    __syncthreads();
    int warp = threadIdx.x >> 5, lane = threadIdx.x & 31;
    int row = blockIdx.x * 8 + warp;
    if (row >= n) return;
    float2 xv = *(const float2*)(x + (size_t)row * D + lane * 2);
    float a0 = 0.f, a1 = 0.f, b0 = 0.f, b1 = 0.f, c0 = 0.f, c1 = 0.f;
#pragma unroll
    for (int k = 0; k < D; k++) {
        float xk = __shfl_sync(0xffffffffu, (k & 1) ? xv.y : xv.x, k >> 1);
        a0 += xk * sW[0][k][lane];      a1 += xk * sW[0][k][lane + 32];
        b0 += xk * sW[1][k][lane];      b1 += xk * sW[1][k][lane + 32];
        c0 += xk * sW[2][k][lane];      c1 += xk * sW[2][k][lane + 32];
    }
    size_t o = (size_t)row * 64;
    g_xwp[o + lane]      = __floats2half2_rn(a0, b0);
    g_xwp[o + lane + 32] = __floats2half2_rn(a1, b1);
    g_mlp[o + lane] = fmaxf(c0, 0.f);
    g_mlp[o + lane + 32] = fmaxf(c1, 0.f);
}

// pass1: dst-grouped gather SpMM with index-broadcast. 16 threads/node, fp32 accum.
__global__ void spmm_gather_kernel(int n) {
    int t = blockIdx.x * blockDim.x + threadIdx.x;
    int node = t >> 4;
    if (node >= n) return;
    int l16 = t & 15;
    unsigned gmask = 0xFFFFu << (threadIdx.x & 16);  // this 16-lane group's mask
    int start = g_rowstart[node];
    int deg = g_deg[node];
    const float4* base = (const float4*)g_xwp;
    float2 a0 = make_float2(0.f, 0.f), a1 = a0, a2 = a0, a3 = a0;
    for (int bse = 0; bse < deg; bse += 16) {
        // one coalesced 8B load per lane covers 16 edges for the whole group
        int2 ed = (bse + l16 < deg) ? g_cedge[start + bse + l16] : make_int2(0, 0);
        int cnt = min(16, deg - bse);
#pragma unroll 4
        for (int i = 0; i < cnt; i++) {
            int sw = __shfl_sync(gmask, ed.x, i, 16);
            int cvb = __shfl_sync(gmask, ed.y, i, 16);
            int s = sw & 0xFFFFF;
            float2 vv = __half22float2(*(__half2*)&cvb);
            float4 raw = base[(size_t)s * 16 + l16];
            float2 f0 = __half22float2(((__half2*)&raw)[0]);
            float2 f1 = __half22float2(((__half2*)&raw)[1]);
            float2 f2 = __half22float2(((__half2*)&raw)[2]);
            float2 f3 = __half22float2(((__half2*)&raw)[3]);
            a0.x += vv.x * f0.x; a0.y += vv.y * f0.y;
            a1.x += vv.x * f1.x; a1.y += vv.y * f1.y;
            a2.x += vv.x * f2.x; a2.y += vv.y * f2.y;
            a3.x += vv.x * f3.x; a3.y += vv.y * f3.y;
        }
    }
    float4 pk;
    ((__half2*)&pk)[0] = __floats2half2_rn(fmaxf(a0.x, 0.f), fmaxf(a0.y, 0.f));
    ((__half2*)&pk)[1] = __floats2half2_rn(fmaxf(a1.x, 0.f), fmaxf(a1.y, 0.f));
    ((__half2*)&pk)[2] = __floats2half2_rn(fmaxf(a2.x, 0.f), fmaxf(a2.y, 0.f));
    ((__half2*)&pk)[3] = __floats2half2_rn(fmaxf(a3.x, 0.f), fmaxf(a3.y, 0.f));
    ((float4*)g_rel)[(size_t)node * 16 + l16] = pk;
}

// pass2 fused with epilogue: bucket sums in registers (index-broadcast gather),
// logits via width-16 shuffles, softmax, combine, one float4 store. 16 thr/node.
__global__ void agg_final_kernel(const float* __restrict__ alf, const float* __restrict__ ahf,
                                 const float* __restrict__ alb, const float* __restrict__ ahb,
                                 const float* __restrict__ alu, const float* __restrict__ ahu,
                                 const float* __restrict__ am,  const float* __restrict__ a7,
                                 float* __restrict__ out, int n) {
    __shared__ float sV[7][D];   // slot order: alf,ahf,alb,ahb,alu,ahu,am
    __shared__ float sA7[49];
    if (threadIdx.x < D) {
        int c = threadIdx.x;
        sV[0][c] = alf[c]; sV[1][c] = ahf[c]; sV[2][c] = alb[c];
        sV[3][c] = ahb[c]; sV[4][c] = alu[c]; sV[5][c] = ahu[c];
        sV[6][c] = am[c];
    }
    if (threadIdx.x < 49) sA7[threadIdx.x] = a7[threadIdx.x];
    __syncthreads();
    int t = blockIdx.x * blockDim.x + threadIdx.x;
    int node = t >> 4;
    if (node >= n) return;
    int l16 = t & 15;
    unsigned gmask = 0xFFFFu << (threadIdx.x & 16);
    int start = g_rowstart[node];
    int deg = g_deg[node];
    const float4* base = (const float4*)g_rel;

    __half2 z = __float2half2_rn(0.f);
    __half2 ho[4] = {z, z, z, z}, he[4] = {z, z, z, z}, un[4] = {z, z, z, z};
    for (int bse = 0; bse < deg; bse += 16) {
        int swm = (bse + l16 < deg) ? g_cedge[start + bse + l16].x : 0;
        int cnt = min(16, deg - bse);
#pragma unroll 4
        for (int i = 0; i < cnt; i++) {
            int sw = __shfl_sync(gmask, swm, i, 16);
            int s = sw & 0xFFFFF;
            int k = sw >> 20;
            float4 raw = base[(size_t)s * 16 + l16];
            __half2 h0 = ((__half2*)&raw)[0];
            __half2 h1 = ((__half2*)&raw)[1];
            __half2 h2 = ((__half2*)&raw)[2];
            __half2 h3 = ((__half2*)&raw)[3];
            if (k == 0) {
                ho[0] = __hadd2(ho[0], h0); ho[1] = __hadd2(ho[1], h1);
                ho[2] = __hadd2(ho[2], h2); ho[3] = __hadd2(ho[3], h3);
            } else if (k == 1) {
                he[0] = __hadd2(he[0], h0); he[1] = __hadd2(he[1], h1);
                he[2] = __hadd2(he[2], h2); he[3] = __hadd2(he[3], h3);
            } else {
                un[0] = __hadd2(un[0], h0); un[1] = __hadd2(un[1], h1);
                un[2] = __hadd2(un[2], h2); un[3] = __hadd2(un[3], h3);
            }
        }
    }

    int c = l16 * 4;
    float4 m4 = ((const float4*)g_mlp)[(size_t)node * 16 + l16];
    const float* mp = (const float*)&m4;

    float ps[7] = {0.f, 0.f, 0.f, 0.f, 0.f, 0.f, 0.f};
#pragma unroll
    for (int j = 0; j < 4; j++) {
        float2 hef = __half22float2(he[j]);
        float2 hof = __half22float2(ho[j]);
        float2 unf = __half22float2(un[j]);
        ps[0] += hef.x * sV[0][c + j];
        ps[1] += hef.y * sV[1][c + j];
        ps[2] += hof.x * sV[2][c + j];
        ps[3] += hof.y * sV[3][c + j];
        ps[4] += unf.x * sV[4][c + j];
        ps[5] += unf.y * sV[5][c + j];
        ps[6] += mp[j] * sV[6][c + j];
    }
#pragma unroll
    for (int off = 8; off; off >>= 1)
#pragma unroll
        for (int j = 0; j < 7; j++)
            ps[j] += __shfl_xor_sync(0xffffffffu, ps[j], off, 16);

    float f[7];
#pragma unroll
    for (int j = 0; j < 7; j++)
        f[j] = 1.f / (1.f + __expf(-ps[j]));
    float lg[7];
    float m = -1e30f;
#pragma unroll
    for (int i = 0; i < 7; i++) {
        float s = 0.f;
#pragma unroll
        for (int j = 0; j < 7; j++) s += f[j] * sA7[j * 7 + i];
        lg[i] = s * (1.0f / 7.0f);
        m = fmaxf(m, lg[i]);
    }
    float sum = 0.f;
#pragma unroll
    for (int i = 0; i < 7; i++) { lg[i] = __expf(lg[i] - m); sum += lg[i]; }
    float inv = 7.0f / sum;
#pragma unroll
    for (int i = 0; i < 7; i++) lg[i] *= inv;

    float4 r;
    float* rp = (float*)&r;
#pragma unroll
    for (int j = 0; j < 4; j++) {
        float2 hef = __half22float2(he[j]);
        float2 hof = __half22float2(ho[j]);
        float2 unf = __half22float2(un[j]);
        rp[j] = lg[0] * hef.x + lg[1] * hef.y + lg[2] * hof.x + lg[3] * hof.y
              + lg[4] * unf.x + lg[5] * unf.y + lg[6] * mp[j];
    }
    ((float4*)out)[(size_t)node * 16 + l16] = r;
}

extern "C" void kernel_launch(void* const* d_in, const int* in_sizes, int n_in,
                              void* d_out, int out_size) {
    const float* x   = (const float*)d_in[0];
    const float* vl  = (const float*)d_in[1];
    const float* vh  = (const float*)d_in[2];
    const float* wl  = (const float*)d_in[3];
    const float* wh  = (const float*)d_in[4];
    const float* wm  = (const float*)d_in[5];
    const float* alf = (const float*)d_in[6];
    const float* ahf = (const float*)d_in[7];
    const float* alb = (const float*)d_in[8];
    const float* ahb = (const float*)d_in[9];
    const float* alu = (const float*)d_in[10];
    const float* ahu = (const float*)d_in[11];
    const float* am  = (const float*)d_in[12];
    const float* a7  = (const float*)d_in[13];
    const int* src   = (const int*)d_in[14];
    const int* dst   = (const int*)d_in[15];
    const int* lab   = (const int*)d_in[16];
    int n = in_sizes[0] / D;
    int e = in_sizes[14];
    float* out = (float*)d_out;

    zero_deg_kernel<<<(n + 255) / 256, 256>>>(n);
    hist_kernel<<<(e + 255) / 256, 256>>>(dst, e);
    scan_kernel<<<1, 1024>>>(n);
    scatter_kernel<<<(e + 255) / 256, 256>>>(src, dst, lab, vl, vh, e);
    gemm3_kernel<<<(n + 7) / 8, 256>>>(x, wl, wh, wm, n);
    int nt = n * 16;
    spmm_gather_kernel<<<(nt + 255) / 256, 256>>>(n);
    agg_final_kernel<<<(nt + 255) / 256, 256>>>(alf, ahf, alb, ahb, alu, ahu, am, a7, out, n);
}

// round 10
// speedup vs baseline: 1.1972x; 1.1972x over previous
#include <cuda_runtime.h>
#include <cuda_fp16.h>
#include <math.h>

#define D 64
#define NMAX 100000
#define EMAX 1600000

// Scratch (__device__ globals, allocation-free rule)
__device__ __half2 g_xwp[(size_t)NMAX * 64];   // (xw_low[c], xw_high[c]) per col
__device__ float   g_mlp[(size_t)NMAX * 64];   // relu(x@W_mlp)
__device__ __half2 g_acc[(size_t)NMAX * 64];   // SpMM accum, packed (low, high), fp16 atomics
__device__ __half2 g_B[3ULL * NMAX * 64];      // bucket sums, packed (low, high)
__device__ int4    g_rec[EMAX];                // {src|k<<20, dst, half2(vl,vh) bits, 0}

__device__ __forceinline__ void redh8(__half2* a, unsigned x, unsigned y, unsigned z, unsigned w) {
    asm volatile("red.global.add.noftz.v4.f16x2 [%0], {%1, %2, %3, %4};"
                 :: "l"(a), "r"(x), "r"(y), "r"(z), "r"(w) : "memory");
}

__global__ void __launch_bounds__(256) zero_kernel(int n) {
    int i = blockIdx.x * blockDim.x + threadIdx.x;
    int nacc = n * 16;                 // float4s in g_acc
    if (i < nacc) {
        ((float4*)g_acc)[i] = make_float4(0.f, 0.f, 0.f, 0.f);
    } else {
        int j = i - nacc;
        if (j < n * 48)
            ((float4*)g_B)[j] = make_float4(0.f, 0.f, 0.f, 0.f);
    }
}

// prep: build 16B edge records once. 1 thread/edge.
__global__ void __launch_bounds__(256) prep_kernel(const int* __restrict__ src,
                                                   const int* __restrict__ dst,
                                                   const int* __restrict__ lab,
                                                   const float* __restrict__ vl,
                                                   const float* __restrict__ vh,
                                                   int e) {
    int i = blockIdx.x * blockDim.x + threadIdx.x;
    if (i >= e) return;
    int s = src[i], d = dst[i];
    int sl = lab[s], dl = lab[d];
    int k = ((sl | dl) < 0) ? 2 : ((sl != dl) ? 1 : 0);
    __half2 cv = __floats2half2_rn(vl[i], vh[i]);
    g_rec[i] = make_int4(s | (k << 20), d, *(int*)&cv, 0);
}

// 3 fused GEMMs: warp per row, weights staged in shared. Low/high packed to half2.
__global__ void __launch_bounds__(256) gemm3_kernel(const float* __restrict__ x,
                                                    const float* __restrict__ wl,
                                                    const float* __restrict__ wh,
                                                    const float* __restrict__ wm,
                                                    int n) {
    __shared__ float sW[3][D][D];
    for (int i = threadIdx.x; i < D * D; i += blockDim.x) {
        sW[0][i >> 6][i & 63] = wl[i];
        sW[1][i >> 6][i & 63] = wh[i];
        sW[2][i >> 6][i & 63] = wm[i];
    }
    __syncthreads();
    int warp = threadIdx.x >> 5, lane = threadIdx.x & 31;
    int row = blockIdx.x * 8 + warp;
    if (row >= n) return;
    float2 xv = *(const float2*)(x + (size_t)row * D + lane * 2);
    float a0 = 0.f, a1 = 0.f, b0 = 0.f, b1 = 0.f, c0 = 0.f, c1 = 0.f;
#pragma unroll
    for (int k = 0; k < D; k++) {
        float xk = __shfl_sync(0xffffffffu, (k & 1) ? xv.y : xv.x, k >> 1);
        a0 += xk * sW[0][k][lane];      a1 += xk * sW[0][k][lane + 32];
        b0 += xk * sW[1][k][lane];      b1 += xk * sW[1][k][lane + 32];
        c0 += xk * sW[2][k][lane];      c1 += xk * sW[2][k][lane + 32];
    }
    size_t o = (size_t)row * 64;
    g_xwp[o + lane]      = __floats2half2_rn(a0, b0);
    g_xwp[o + lane + 32] = __floats2half2_rn(a1, b1);
    g_mlp[o + lane] = fmaxf(c0, 0.f);
    g_mlp[o + lane + 32] = fmaxf(c1, 0.f);
}

// pass1: edge-parallel SpMM. 16 threads/edge; record broadcast + ONE fp16x8 red.
__global__ void __launch_bounds__(256) spmm_kernel(int e) {
    int tid = blockIdx.x * blockDim.x + threadIdx.x;
    int eid = tid >> 4;
    if (eid >= e) return;
    int c4 = tid & 15;
    int4 rec = g_rec[eid];            // same 16B for all 16 lanes -> broadcast sector
    int s = rec.x & 0xFFFFF;
    __half2 cf = *(__half2*)&rec.z;
    float4 raw = ((const float4*)g_xwp)[(size_t)s * 16 + c4];
    __half2 p0 = __hmul2(*(__half2*)&raw.x, cf);
    __half2 p1 = __hmul2(*(__half2*)&raw.y, cf);
    __half2 p2 = __hmul2(*(__half2*)&raw.z, cf);
    __half2 p3 = __hmul2(*(__half2*)&raw.w, cf);
    redh8(g_acc + (size_t)rec.y * 64 + c4 * 4,
          *(unsigned*)&p0, *(unsigned*)&p1, *(unsigned*)&p2, *(unsigned*)&p3);
}

// pass2: bucketed aggregation; relu on the gather. 16 threads/edge.
__global__ void __launch_bounds__(256) pass2_kernel(int e) {
    int tid = blockIdx.x * blockDim.x + threadIdx.x;
    int eid = tid >> 4;
    if (eid >= e) return;
    int c4 = tid & 15;
    int4 rec = g_rec[eid];
    int s = rec.x & 0xFFFFF;
    int k = rec.x >> 20;
    float4 raw = ((const float4*)g_acc)[(size_t)s * 16 + c4];
    __half2 z = __float2half2_rn(0.f);
    __half2 p0 = __hmax2(*(__half2*)&raw.x, z);
    __half2 p1 = __hmax2(*(__half2*)&raw.y, z);
    __half2 p2 = __hmax2(*(__half2*)&raw.z, z);
    __half2 p3 = __hmax2(*(__half2*)&raw.w, z);
    redh8(g_B + (size_t)k * NMAX * 64 + (size_t)rec.y * 64 + c4 * 4,
          *(unsigned*)&p0, *(unsigned*)&p1, *(unsigned*)&p2, *(unsigned*)&p3);
}

// nodeB: streamed epilogue — logits from bucket dots, softmax, combine. Warp/node.
__global__ void __launch_bounds__(256) nodeB_kernel(
        const float* __restrict__ alf, const float* __restrict__ ahf,
        const float* __restrict__ alb, const float* __restrict__ ahb,
        const float* __restrict__ alu, const float* __restrict__ ahu,
        const float* __restrict__ am,  const float* __restrict__ a7,
        float* __restrict__ out, int n) {
    __shared__ float sV[7][D];   // slot order: alf,ahf,alb,ahb,alu,ahu,am
    __shared__ float sA7[49];
    if (threadIdx.x < D) {
        int c = threadIdx.x;
        sV[0][c] = alf[c]; sV[1][c] = ahf[c]; sV[2][c] = alb[c];
        sV[3][c] = ahb[c]; sV[4][c] = alu[c]; sV[5][c] = ahu[c];
        sV[6][c] = am[c];
    }
    if (threadIdx.x < 49) sA7[threadIdx.x] = a7[threadIdx.x];
    __syncthreads();
    int warp = threadIdx.x >> 5, lane = threadIdx.x & 31;
    int node = blockIdx.x * 8 + warp;
    if (node >= n) return;
    int c = lane * 2;
    size_t o = (size_t)node * 64;
    float2 homo2 = ((const float2*)(g_B + 0ULL * NMAX * 64 + o))[lane];
    float2 hete2 = ((const float2*)(g_B + 1ULL * NMAX * 64 + o))[lane];
    float2 unk2  = ((const float2*)(g_B + 2ULL * NMAX * 64 + o))[lane];
    float2 m2    = ((const float2*)(g_mlp + o))[lane];
    float2 hoA = __half22float2(((__half2*)&homo2)[0]);  // x=low[c], y=high[c]
    float2 hoB = __half22float2(((__half2*)&homo2)[1]);  // col c+1
    float2 heA = __half22float2(((__half2*)&hete2)[0]);
    float2 heB = __half22float2(((__half2*)&hete2)[1]);
    float2 unA = __half22float2(((__half2*)&unk2)[0]);
    float2 unB = __half22float2(((__half2*)&unk2)[1]);

    float ps[7];
    ps[0] = heA.x * sV[0][c] + heB.x * sV[0][c + 1];
    ps[1] = heA.y * sV[1][c] + heB.y * sV[1][c + 1];
    ps[2] = hoA.x * sV[2][c] + hoB.x * sV[2][c + 1];
    ps[3] = hoA.y * sV[3][c] + hoB.y * sV[3][c + 1];
    ps[4] = unA.x * sV[4][c] + unB.x * sV[4][c + 1];
    ps[5] = unA.y * sV[5][c] + unB.y * sV[5][c + 1];
    ps[6] = m2.x  * sV[6][c] + m2.y  * sV[6][c + 1];
#pragma unroll
    for (int off = 16; off; off >>= 1)
#pragma unroll
        for (int j = 0; j < 7; j++)
            ps[j] += __shfl_xor_sync(0xffffffffu, ps[j], off);

    float f[7];
#pragma unroll
    for (int j = 0; j < 7; j++)
        f[j] = 1.f / (1.f + __expf(-ps[j]));
    float lg[7];
    float m = -1e30f;
#pragma unroll
    for (int i = 0; i < 7; i++) {
        float s = 0.f;
#pragma unroll
        for (int j = 0; j < 7; j++) s += f[j] * sA7[j * 7 + i];
        lg[i] = s * (1.0f / 7.0f);
        m = fmaxf(m, lg[i]);
    }
    float sum = 0.f;
#pragma unroll
    for (int i = 0; i < 7; i++) { lg[i] = __expf(lg[i] - m); sum += lg[i]; }
    float inv = 7.0f / sum;
#pragma unroll
    for (int i = 0; i < 7; i++) lg[i] *= inv;

    float2 r;
    r.x = lg[0] * heA.x + lg[1] * heA.y + lg[2] * hoA.x + lg[3] * hoA.y
        + lg[4] * unA.x + lg[5] * unA.y + lg[6] * m2.x;
    r.y = lg[0] * heB.x + lg[1] * heB.y + lg[2] * hoB.x + lg[3] * hoB.y
        + lg[4] * unB.x + lg[5] * unB.y + lg[6] * m2.y;
    *(float2*)(out + o + c) = r;
}

extern "C" void kernel_launch(void* const* d_in, const int* in_sizes, int n_in,
                              void* d_out, int out_size) {
    const float* x   = (const float*)d_in[0];
    const float* vl  = (const float*)d_in[1];
    const float* vh  = (const float*)d_in[2];
    const float* wl  = (const float*)d_in[3];
    const float* wh  = (const float*)d_in[4];
    const float* wm  = (const float*)d_in[5];
    const float* alf = (const float*)d_in[6];
    const float* ahf = (const float*)d_in[7];
    const float* alb = (const float*)d_in[8];
    const float* ahb = (const float*)d_in[9];
    const float* alu = (const float*)d_in[10];
    const float* ahu = (const float*)d_in[11];
    const float* am  = (const float*)d_in[12];
    const float* a7  = (const float*)d_in[13];
    const int* src   = (const int*)d_in[14];
    const int* dst   = (const int*)d_in[15];
    const int* lab   = (const int*)d_in[16];
    int n = in_sizes[0] / D;
    int e = in_sizes[14];
    float* out = (float*)d_out;

    int nz = n * 64;  // float4s: acc (16/node) + 3 bucket slabs (16/node each)
    zero_kernel<<<(nz + 255) / 256, 256>>>(n);
    prep_kernel<<<(e + 255) / 256, 256>>>(src, dst, lab, vl, vh, e);
    gemm3_kernel<<<(n + 7) / 8, 256>>>(x, wl, wh, wm, n);
    int et = e * 16;
    spmm_kernel<<<(et + 255) / 256, 256>>>(e);
    pass2_kernel<<<(et + 255) / 256, 256>>>(e);
    nodeB_kernel<<<(n + 7) / 8, 256>>>(alf, ahf, alb, ahb, alu, ahu, am, a7, out, n);
}